// round 2
// baseline (speedup 1.0000x reference)
#include <cuda_runtime.h>
#include <math_constants.h>

#define POOL 7
#define NUM_ROIS 300
#define HH 50
#define WW 50
#define CC 512
#define NPIX (HH * WW)
#define NBINS (POOL * POOL)

// Scratch: channel-max per pixel (10 KB). __device__ global (no allocation).
__device__ float g_fmax[NPIX];

// K1: one warp per pixel, reduce 512 contiguous fp32 -> 1 fp32.
__global__ void fmax_kernel(const float* __restrict__ fm) {
    int gwarp = (blockIdx.x * blockDim.x + threadIdx.x) >> 5;
    int lane  = threadIdx.x & 31;
    if (gwarp >= NPIX) return;
    const float4* p = reinterpret_cast<const float4*>(fm + (size_t)gwarp * CC);
    float m = -CUDART_INF_F;
#pragma unroll
    for (int i = 0; i < 4; i++) {
        float4 v = p[lane + i * 32];              // coalesced 128B per iter per warp
        m = fmaxf(m, fmaxf(fmaxf(v.x, v.y), fmaxf(v.z, v.w)));
    }
#pragma unroll
    for (int s = 16; s; s >>= 1)
        m = fmaxf(m, __shfl_xor_sync(0xffffffffu, m, s));
    if (lane == 0) g_fmax[gwarp] = m;
}

// K2: one block per (roi, bin). Compute bin spatial max over g_fmax, then
// broadcast to 512 channels with float4 stores (128 thr x 16B = 2048B).
__global__ void __launch_bounds__(128) pool_bcast_kernel(
    const float* __restrict__ rois, float* __restrict__ out) {
    int b   = blockIdx.x;            // 0 .. NUM_ROIS*NBINS-1
    int roi = b / NBINS;
    int bin = b - roi * NBINS;
    int bi  = bin / POOL;
    int bj  = bin - bi * POOL;

    const float inv = 1.0f / 16.0f;
    int x1 = (int)(rois[roi * 5 + 1] * inv);
    int y1 = (int)(rois[roi * 5 + 2] * inv);
    int x2 = (int)(rois[roi * 5 + 3] * inv);
    int y2 = (int)(rois[roi * 5 + 4] * inv);
    int rh = y2 - y1 + 1;
    int rw = x2 - x1 + 1;

    int hs = min(max(y1 + (bi * rh) / POOL, 0), HH);
    int he = min(max(y1 + ((bi + 1) * rh + POOL - 1) / POOL, 0), HH);
    int ws = min(max(x1 + (bj * rw) / POOL, 0), WW);
    int we = min(max(x1 + ((bj + 1) * rw + POOL - 1) / POOL, 0), WW);

    int nh = he - hs;
    int nw = we - ws;
    int n  = (nh > 0 && nw > 0) ? nh * nw : 0;

    int tid = threadIdx.x;
    float m = -CUDART_INF_F;
    for (int idx = tid; idx < n; idx += 128) {   // region <= 64 cells: <=1 iter/thread
        int r = hs + idx / nw;
        int c = ws + (idx - (idx / nw) * nw);
        m = fmaxf(m, g_fmax[r * WW + c]);
    }
#pragma unroll
    for (int s = 16; s; s >>= 1)
        m = fmaxf(m, __shfl_xor_sync(0xffffffffu, m, s));

    __shared__ float sm[4];
    if ((tid & 31) == 0) sm[tid >> 5] = m;
    __syncthreads();
    float v = fmaxf(fmaxf(sm[0], sm[1]), fmaxf(sm[2], sm[3]));

    float4 o = make_float4(v, v, v, v);
    reinterpret_cast<float4*>(out + (size_t)b * CC)[tid] = o;
}

extern "C" void kernel_launch(void* const* d_in, const int* in_sizes, int n_in,
                              void* d_out, int out_size) {
    // metadata order: rois (300*5=1500), feature_maps (50*50*512). Defensive swap by size.
    const float* rois = (const float*)d_in[0];
    const float* fm   = (const float*)d_in[1];
    if (in_sizes[0] != NUM_ROIS * 5) {
        const float* t = rois; rois = fm; fm = t;
    }
    float* out = (float*)d_out;

    int threads1 = 256;                                  // 8 warps/block
    int blocks1  = (NPIX * 32 + threads1 - 1) / threads1; // 2500 warps
    fmax_kernel<<<blocks1, threads1>>>(fm);

    pool_bcast_kernel<<<NUM_ROIS * NBINS, 128>>>(rois, out);
}

// round 3
// speedup vs baseline: 1.0993x; 1.0993x over previous
#include <cuda_runtime.h>
#include <math_constants.h>

#define POOL 7
#define NUM_ROIS 300
#define HH 50
#define WW 50
#define CC 512
#define NPIX (HH * WW)
#define NBINS (POOL * POOL)
#define VEC_PER_BIN (CC / 4)            // 128 float4 per bin
#define VEC_PER_ROI (NBINS * VEC_PER_BIN) // 6272 float4 per roi

// Scratch: channel-max per pixel (10 KB). __device__ global (no allocation).
__device__ float g_fmax[NPIX];

// K1: one warp per pixel, reduce 512 contiguous fp32 -> 1 fp32.
__global__ void fmax_kernel(const float* __restrict__ fm) {
    int gwarp = (blockIdx.x * blockDim.x + threadIdx.x) >> 5;
    int lane  = threadIdx.x & 31;
    if (gwarp >= NPIX) return;
    const float4* p = reinterpret_cast<const float4*>(fm + (size_t)gwarp * CC);
    float m = -CUDART_INF_F;
#pragma unroll
    for (int i = 0; i < 4; i++) {
        float4 v = p[lane + i * 32];              // coalesced 128B per iter per warp
        m = fmaxf(m, fmaxf(fmaxf(v.x, v.y), fmaxf(v.z, v.w)));
    }
#pragma unroll
    for (int s = 16; s; s >>= 1)
        m = fmaxf(m, __shfl_xor_sync(0xffffffffu, m, s));
    if (lane == 0) g_fmax[gwarp] = m;
}

// K2: one block per ROI. Stage g_fmax in smem, compute 49 bin maxes, then
// stream 49*512 floats of broadcast output with float4 stores.
__global__ void __launch_bounds__(256) roi_kernel(
    const float* __restrict__ rois, float* __restrict__ out) {
    __shared__ float s_fmax[NPIX];
    __shared__ float s_bin[NBINS];

    int roi = blockIdx.x;
    int tid = threadIdx.x;

    // Phase A1: stage the 10KB fmax plane into smem (coalesced float loads).
    for (int i = tid; i < NPIX; i += 256)
        s_fmax[i] = g_fmax[i];

    // ROI rectangle (all threads compute; cheap, avoids extra smem/sync).
    const float inv = 1.0f / 16.0f;
    int x1 = (int)(rois[roi * 5 + 1] * inv);
    int y1 = (int)(rois[roi * 5 + 2] * inv);
    int x2 = (int)(rois[roi * 5 + 3] * inv);
    int y2 = (int)(rois[roi * 5 + 4] * inv);
    int rh = y2 - y1 + 1;
    int rw = x2 - x1 + 1;
    __syncthreads();

    // Phase A2: threads 0..48 each compute one bin's spatial max from smem.
    if (tid < NBINS) {
        int bi = tid / POOL;
        int bj = tid - bi * POOL;
        int hs = min(max(y1 + (bi * rh) / POOL, 0), HH);
        int he = min(max(y1 + ((bi + 1) * rh + POOL - 1) / POOL, 0), HH);
        int ws = min(max(x1 + (bj * rw) / POOL, 0), WW);
        int we = min(max(x1 + ((bj + 1) * rw + POOL - 1) / POOL, 0), WW);
        float m = -CUDART_INF_F;
        for (int r = hs; r < he; r++)
            for (int c = ws; c < we; c++)
                m = fmaxf(m, s_fmax[r * WW + c]);
        s_bin[tid] = m;
    }
    __syncthreads();

    // Phase B: stream 6272 float4 (98KB) of broadcast output, fully coalesced.
    float4* out4 = reinterpret_cast<float4*>(out) + (size_t)roi * VEC_PER_ROI;
#pragma unroll 4
    for (int i = tid; i < VEC_PER_ROI; i += 256) {
        float v = s_bin[i >> 7];                  // i / VEC_PER_BIN
        out4[i] = make_float4(v, v, v, v);
    }
}

extern "C" void kernel_launch(void* const* d_in, const int* in_sizes, int n_in,
                              void* d_out, int out_size) {
    const float* rois = (const float*)d_in[0];
    const float* fm   = (const float*)d_in[1];
    if (in_sizes[0] != NUM_ROIS * 5) {
        const float* t = rois; rois = fm; fm = t;
    }
    float* out = (float*)d_out;

    int threads1 = 256;
    int blocks1  = (NPIX * 32 + threads1 - 1) / threads1; // one warp per pixel
    fmax_kernel<<<blocks1, threads1>>>(fm);

    roi_kernel<<<NUM_ROIS, 256>>>(rois, out);
}